// round 5
// baseline (speedup 1.0000x reference)
#include <cuda_runtime.h>
#include <cuda_bf16.h>
#include <cstdint>

// ---------------------------------------------------------------------------
// AttnBlock, Round 4: all GEMMs on mma.sync bf16 (tcgen05 unavailable: harness
// emits compute_100 PTX). Conv = implicit GEMM, direct gather from transposed
// x (no im2col), 128x256 CTA tile, 512 threads, cp.async double buffering.
// ---------------------------------------------------------------------------

#define Bsz 16
#define C 512
#define HW 1024
#define C3 1536
#define KTOT 4608        // 512*9

#define BM 128
#define BN 128
#define BK 32
#define BKP 40
#define SP  136

#define CBN 256          // conv CTA N-tile

// Scratch: device globals (no allocation allowed)
__device__ __nv_bfloat16 g_wpack[C3 * KTOT];                 // [oc][tap*512+ic]
__device__ __nv_bfloat16 g_wproj[C * C];
__device__ __nv_bfloat16 g_xt[(size_t)Bsz * HW * C];         // [b][p][c] bf16
__device__ __nv_bfloat16 g_qkv[(size_t)Bsz * C3 * HW];       // [b][3C][p]
__device__ float         g_scores[(size_t)Bsz * HW * HW];
__device__ __nv_bfloat16 g_attn[(size_t)Bsz * HW * HW];
__device__ __nv_bfloat16 g_h[(size_t)Bsz * HW * C];

// ---------------------------------------------------------------------------
// PTX helpers
// ---------------------------------------------------------------------------
__device__ __forceinline__ unsigned su32(const void* p) {
    unsigned a;
    asm("{ .reg .u64 t; cvta.to.shared.u64 t, %1; cvt.u32.u64 %0, t; }"
        : "=r"(a) : "l"(p));
    return a;
}
__device__ __forceinline__ void cp16(unsigned dst, const void* src) {
    asm volatile("cp.async.cg.shared.global [%0], [%1], 16;" :: "r"(dst), "l"(src));
}
__device__ __forceinline__ void cp16z(unsigned dst, const void* src, unsigned sz) {
    asm volatile("cp.async.cg.shared.global [%0], [%1], 16, %2;"
                 :: "r"(dst), "l"(src), "r"(sz));
}
#define CP_COMMIT() asm volatile("cp.async.commit_group;")
#define CP_WAIT0()  asm volatile("cp.async.wait_group 0;")

__device__ __forceinline__ void ldsm_x4(unsigned* r, unsigned addr) {
    asm volatile("ldmatrix.sync.aligned.m8n8.x4.shared.b16 {%0,%1,%2,%3}, [%4];"
                 : "=r"(r[0]), "=r"(r[1]), "=r"(r[2]), "=r"(r[3]) : "r"(addr));
}
__device__ __forceinline__ void ldsm_x4_t(unsigned* r, unsigned addr) {
    asm volatile("ldmatrix.sync.aligned.m8n8.x4.trans.shared.b16 {%0,%1,%2,%3}, [%4];"
                 : "=r"(r[0]), "=r"(r[1]), "=r"(r[2]), "=r"(r[3]) : "r"(addr));
}
__device__ __forceinline__ void mma16816(float* d, const unsigned* a, const unsigned* b) {
    asm volatile(
        "mma.sync.aligned.m16n8k16.row.col.f32.bf16.bf16.f32 "
        "{%0,%1,%2,%3},{%4,%5,%6,%7},{%8,%9},{%0,%1,%2,%3};"
        : "+f"(d[0]), "+f"(d[1]), "+f"(d[2]), "+f"(d[3])
        : "r"(a[0]), "r"(a[1]), "r"(a[2]), "r"(a[3]), "r"(b[0]), "r"(b[1]));
}

// One BK=32 slab: per-warp 32x64 tile. AT: A smem [BK][128+8] k-major (trans);
// else [rows][BK+8]. BT likewise.
template <bool AT, bool BT>
__device__ __forceinline__ void mma_block(unsigned aB, unsigned bB,
                                          float acc[2][8][4], int lane, int wm, int wn) {
    const int g = lane >> 3, r = lane & 7;
#pragma unroll
    for (int ks = 0; ks < 2; ks++) {
        const int k = ks * 16;
        unsigned a[2][4];
#pragma unroll
        for (int mi = 0; mi < 2; mi++) {
            const int mt = wm * 32 + mi * 16;
            if (AT) {
                unsigned off = ((k + (g >> 1) * 8 + r) * SP + mt + (g & 1) * 8) * 2;
                ldsm_x4_t(a[mi], aB + off);
            } else {
                unsigned off = ((mt + (g & 1) * 8 + r) * BKP + k + (g >> 1) * 8) * 2;
                ldsm_x4(a[mi], aB + off);
            }
        }
        unsigned bf[8][2];
#pragma unroll
        for (int nj = 0; nj < 4; nj++) {
            const int nt = wn * 64 + nj * 16;
            unsigned t[4];
            if (BT) {
                unsigned off = ((k + (g & 1) * 8 + r) * SP + nt + (g >> 1) * 8) * 2;
                ldsm_x4_t(t, bB + off);
            } else {
                unsigned off = ((nt + (g >> 1) * 8 + r) * BKP + k + (g & 1) * 8) * 2;
                ldsm_x4(t, bB + off);
            }
            bf[nj * 2][0] = t[0]; bf[nj * 2][1] = t[1];
            bf[nj * 2 + 1][0] = t[2]; bf[nj * 2 + 1][1] = t[3];
        }
#pragma unroll
        for (int mi = 0; mi < 2; mi++)
#pragma unroll
            for (int n = 0; n < 8; n++) mma16816(acc[mi][n], a[mi], bf[n]);
    }
}

// ---------------------------------------------------------------------------
// Prep kernels
// ---------------------------------------------------------------------------
__global__ void pack_w_kernel(const float* __restrict__ w) {
    int i = blockIdx.x * blockDim.x + threadIdx.x;
    if (i >= C3 * KTOT) return;
    int oc = i / KTOT;
    int r = i - oc * KTOT;
    int tap = r >> 9, ic = r & 511;
    g_wpack[i] = __float2bfloat16(w[oc * KTOT + ic * 9 + tap]);
}
__global__ void pack_wproj_kernel(const float* __restrict__ w) {
    int i = blockIdx.x * blockDim.x + threadIdx.x;
    if (i < C * C) g_wproj[i] = __float2bfloat16(w[i]);
}
// x [b][c][p] f32 -> g_xt [b][p][c] bf16, 64x64 tiles via smem
__global__ void xt_kernel(const float* __restrict__ x) {
    __shared__ float st[64][65];
    const int b = blockIdx.z, c0 = blockIdx.y * 64, p0 = blockIdx.x * 64;
    const int tid = threadIdx.x;
    const int pi = tid & 63, cj = tid >> 6;    // cj 0..3
#pragma unroll
    for (int jj = 0; jj < 16; jj++) {
        int c = cj * 16 + jj;
        st[pi][c] = x[((size_t)b * C + c0 + c) * HW + p0 + pi];
    }
    __syncthreads();
    const int pr = tid >> 2, cc = (tid & 3) * 16;
    __nv_bfloat16 v[16];
#pragma unroll
    for (int j = 0; j < 16; j++) v[j] = __float2bfloat16(st[pr][cc + j]);
    __nv_bfloat16* dst = g_xt + ((size_t)b * HW + p0 + pr) * C + c0 + cc;
    *(uint4*)dst = *(uint4*)v;
    *(uint4*)(dst + 8) = *(uint4*)(v + 8);
}

// ---------------------------------------------------------------------------
// conv3x3 implicit GEMM: qkv[oc][p] = wpack[oc][k] @ gather(x_t)[k][p] + bias
// CTA 128x256, 512 threads (warps 4m x 4n, 32x64 each), BK=32, 2-stage.
// A smem [128][BKP] row-major; B smem [256][BKP]: row=pixel, cols=32 ic of the
// slab's tap, gathered from g_xt with border zero-fill.
// ---------------------------------------------------------------------------
#define CA_ST (BM * BKP)                // 5120 elems / stage
#define CB_ST (CBN * BKP)               // 10240 elems / stage
#define SMEM_CONV ((2 * CA_ST + 2 * CB_ST) * 2)   // 61440 bytes

__global__ __launch_bounds__(512, 1)
void conv_mma2(const float* __restrict__ bias) {
    extern __shared__ __align__(16) __nv_bfloat16 cs[];
    __nv_bfloat16* As = cs;                       // [2][CA_ST]
    __nv_bfloat16* Bs = cs + 2 * CA_ST;           // [2][CB_ST]
    const int b = blockIdx.z, m0 = blockIdx.y * BM, n0 = blockIdx.x * CBN;
    const int tid = threadIdx.x, lane = tid & 31, wid = tid >> 5;
    const int wm = wid >> 2, wn = wid & 3;
    const __nv_bfloat16* xbase = g_xt + (size_t)b * HW * C;

    float acc[2][8][4];
#pragma unroll
    for (int i = 0; i < 2; i++)
#pragma unroll
        for (int j = 0; j < 8; j++)
#pragma unroll
            for (int q = 0; q < 4; q++) acc[i][j][q] = 0.f;

    const unsigned aBase = su32(As), bBase = su32(Bs);
    // A: 512 chunks (128 rows x 4): one per thread
    const int ar = tid >> 2, ac = tid & 3;
    // B: 1024 chunks (256 rows x 4): two per thread
    const int brow = tid >> 1, bc0 = (tid & 1) * 2;
    const int px = n0 + brow, ph = px >> 5, pw = px & 31;
    const __nv_bfloat16* aptr = g_wpack + (size_t)(m0 + ar) * KTOT + ac * 8;

    auto issue = [&](int k0, int st) {
        cp16(aBase + (unsigned)(st * CA_ST + ar * BKP + ac * 8) * 2, aptr + k0);
        const int tap = k0 >> 9, ic0 = k0 & 511;
        const int dh = tap / 3 - 1, dw = tap % 3 - 1;
        const int hh = ph + dh, ww = pw + dw;
        const bool ok = ((unsigned)hh < 32u) && ((unsigned)ww < 32u);
        const __nv_bfloat16* src =
            xbase + (size_t)(ok ? ((hh << 5) + ww) : 0) * C + ic0 + bc0 * 8;
        const unsigned sz = ok ? 16u : 0u;
        unsigned bd = bBase + (unsigned)(st * CB_ST + brow * BKP + bc0 * 8) * 2;
        cp16z(bd, src, sz);
        cp16z(bd + 16, src + 8, sz);
        CP_COMMIT();
    };

    issue(0, 0);
    const int S = KTOT / BK;     // 144
    for (int s = 0; s < S; s++) {
        CP_WAIT0();
        __syncthreads();
        if (s + 1 < S) issue((s + 1) * BK, (s + 1) & 1);
        mma_block<false, false>(aBase + (unsigned)((s & 1) * CA_ST) * 2,
                                bBase + (unsigned)((s & 1) * CB_ST) * 2,
                                acc, lane, wm, wn);
    }

    __nv_bfloat16* out = g_qkv + (size_t)b * C3 * HW;
    const int rr = lane >> 2, cc = (lane & 3) * 2;
#pragma unroll
    for (int mi = 0; mi < 2; mi++) {
        int gr = m0 + wm * 32 + mi * 16 + rr;
        float b0v = bias[gr], b1v = bias[gr + 8];
#pragma unroll
        for (int n = 0; n < 8; n++) {
            int gc = n0 + wn * 64 + n * 8 + cc;
            *(__nv_bfloat162*)&out[(size_t)gr * HW + gc] =
                __floats2bfloat162_rn(acc[mi][n][0] + b0v, acc[mi][n][1] + b0v);
            *(__nv_bfloat162*)&out[(size_t)(gr + 8) * HW + gc] =
                __floats2bfloat162_rn(acc[mi][n][2] + b1v, acc[mi][n][3] + b1v);
        }
    }
}

// ---------------------------------------------------------------------------
// scores[qn][km] = scale * q^T k ; q,k are [c][p] (both k-major / trans)
// ---------------------------------------------------------------------------
__global__ __launch_bounds__(256, 2)
void scores_mma() {
    __shared__ __align__(16) __nv_bfloat16 As[2][BK * SP];
    __shared__ __align__(16) __nv_bfloat16 Bs[2][BK * SP];
    const int b = blockIdx.z, m0 = blockIdx.y * BM, n0 = blockIdx.x * BN;
    const int tid = threadIdx.x, lane = tid & 31, wid = tid >> 5;
    const int wm = wid >> 1, wn = wid & 1;
    const __nv_bfloat16* q = g_qkv + (size_t)b * C3 * HW;
    const __nv_bfloat16* km = q + (size_t)C * HW;

    float acc[2][8][4];
#pragma unroll
    for (int i = 0; i < 2; i++)
#pragma unroll
        for (int j = 0; j < 8; j++)
#pragma unroll
            for (int qq = 0; qq < 4; qq++) acc[i][j][qq] = 0.f;

    const unsigned aBase = su32(As), bBase = su32(Bs);
    const int r0 = tid >> 4, qd = tid & 15;

    auto issue = [&](int k0, int st) {
        unsigned off = (unsigned)(r0 * SP + qd * 8) * 2;
        unsigned ad = aBase + (unsigned)(st * BK * SP) * 2 + off;
        unsigned bd = bBase + (unsigned)(st * BK * SP) * 2 + off;
        const __nv_bfloat16* as = &q[(size_t)(k0 + r0) * HW + m0 + qd * 8];
        const __nv_bfloat16* bs = &km[(size_t)(k0 + r0) * HW + n0 + qd * 8];
        cp16(ad, as);                        cp16(bd, bs);
        cp16(ad + 16 * SP * 2, as + (size_t)16 * HW);
        cp16(bd + 16 * SP * 2, bs + (size_t)16 * HW);
        CP_COMMIT();
    };

    issue(0, 0);
    const int S = C / BK;
    for (int s = 0; s < S; s++) {
        CP_WAIT0();
        __syncthreads();
        if (s + 1 < S) issue((s + 1) * BK, (s + 1) & 1);
        mma_block<true, true>(aBase + (unsigned)((s & 1) * BK * SP) * 2,
                              bBase + (unsigned)((s & 1) * BK * SP) * 2,
                              acc, lane, wm, wn);
    }

    const float scale = 0.044194173824159216f;
    float* sp = g_scores + (size_t)b * HW * HW;
    const int rr = lane >> 2, cc = (lane & 3) * 2;
#pragma unroll
    for (int mi = 0; mi < 2; mi++) {
        int gr = m0 + wm * 32 + mi * 16 + rr;
#pragma unroll
        for (int n = 0; n < 8; n++) {
            int gc = n0 + wn * 64 + n * 8 + cc;
            *(float2*)&sp[(size_t)gr * HW + gc] =
                make_float2(acc[mi][n][0] * scale, acc[mi][n][1] * scale);
            *(float2*)&sp[(size_t)(gr + 8) * HW + gc] =
                make_float2(acc[mi][n][2] * scale, acc[mi][n][3] * scale);
        }
    }
}

// ---------------------------------------------------------------------------
__global__ void softmax_kernel() {
    const float* s = g_scores + (size_t)blockIdx.x * HW;
    __nv_bfloat16* a = g_attn + (size_t)blockIdx.x * HW;
    const int tid = threadIdx.x, lane = tid & 31, wid = tid >> 5;
    __shared__ float red[32];

    float4 v = ((const float4*)s)[tid];
    float mx = fmaxf(fmaxf(v.x, v.y), fmaxf(v.z, v.w));
#pragma unroll
    for (int o = 16; o; o >>= 1) mx = fmaxf(mx, __shfl_xor_sync(0xffffffffu, mx, o));
    if (lane == 0) red[wid] = mx;
    __syncthreads();
    if (wid == 0) {
        float t = (lane < 8) ? red[lane] : -3.4e38f;
#pragma unroll
        for (int o = 4; o; o >>= 1) t = fmaxf(t, __shfl_xor_sync(0xffffffffu, t, o));
        if (lane == 0) red[0] = t;
    }
    __syncthreads();
    mx = red[0];
    __syncthreads();

    float4 e;
    e.x = expf(v.x - mx); e.y = expf(v.y - mx);
    e.z = expf(v.z - mx); e.w = expf(v.w - mx);
    float sum = e.x + e.y + e.z + e.w;
#pragma unroll
    for (int o = 16; o; o >>= 1) sum += __shfl_xor_sync(0xffffffffu, sum, o);
    if (lane == 0) red[wid] = sum;
    __syncthreads();
    if (wid == 0) {
        float t = (lane < 8) ? red[lane] : 0.f;
#pragma unroll
        for (int o = 4; o; o >>= 1) t += __shfl_xor_sync(0xffffffffu, t, o);
        if (lane == 0) red[0] = t;
    }
    __syncthreads();
    float inv = 1.0f / red[0];
    __nv_bfloat162 p0 = __floats2bfloat162_rn(e.x * inv, e.y * inv);
    __nv_bfloat162 p1 = __floats2bfloat162_rn(e.z * inv, e.w * inv);
    ((__nv_bfloat162*)a)[tid * 2] = p0;
    ((__nv_bfloat162*)a)[tid * 2 + 1] = p1;
}

// ---------------------------------------------------------------------------
__global__ __launch_bounds__(256, 2)
void av_mma() {
    __shared__ __align__(16) __nv_bfloat16 As[2][BM * BKP];
    __shared__ __align__(16) __nv_bfloat16 Bs[2][BN * BKP];
    const int b = blockIdx.z, m0 = blockIdx.y * BM, n0 = blockIdx.x * BN;
    const int tid = threadIdx.x, lane = tid & 31, wid = tid >> 5;
    const int wm = wid >> 1, wn = wid & 1;
    const __nv_bfloat16* attn = g_attn + (size_t)b * HW * HW;
    const __nv_bfloat16* v = g_qkv + (size_t)b * C3 * HW + (size_t)2 * C * HW;

    float acc[2][8][4];
#pragma unroll
    for (int i = 0; i < 2; i++)
#pragma unroll
        for (int j = 0; j < 8; j++)
#pragma unroll
            for (int q = 0; q < 4; q++) acc[i][j][q] = 0.f;

    const unsigned aBase = su32(As), bBase = su32(Bs);
    const int ar = tid >> 2, aq = tid & 3;

    auto issue = [&](int k0, int st) {
        unsigned off = (unsigned)(ar * BKP + aq * 8) * 2;
        unsigned ad = aBase + (unsigned)(st * BM * BKP) * 2 + off;
        unsigned bd = bBase + (unsigned)(st * BN * BKP) * 2 + off;
        const __nv_bfloat16* as = &attn[(size_t)(m0 + ar) * HW + k0 + aq * 8];
        const __nv_bfloat16* bs = &v[(size_t)(n0 + ar) * HW + k0 + aq * 8];
        cp16(ad, as);                                 cp16(bd, bs);
        cp16(ad + 64 * BKP * 2, as + (size_t)64 * HW);
        cp16(bd + 64 * BKP * 2, bs + (size_t)64 * HW);
        CP_COMMIT();
    };

    issue(0, 0);
    const int S = HW / BK;
    for (int s = 0; s < S; s++) {
        CP_WAIT0();
        __syncthreads();
        if (s + 1 < S) issue((s + 1) * BK, (s + 1) & 1);
        mma_block<false, false>(aBase + (unsigned)((s & 1) * BM * BKP) * 2,
                                bBase + (unsigned)((s & 1) * BN * BKP) * 2,
                                acc, lane, wm, wn);
    }

    __nv_bfloat16* hp = g_h + (size_t)b * HW * C;
    const int rr = lane >> 2, cc = (lane & 3) * 2;
#pragma unroll
    for (int mi = 0; mi < 2; mi++) {
        int gr = m0 + wm * 32 + mi * 16 + rr;
#pragma unroll
        for (int n = 0; n < 8; n++) {
            int gc = n0 + wn * 64 + n * 8 + cc;
            *(__nv_bfloat162*)&hp[(size_t)gr * C + gc] =
                __floats2bfloat162_rn(acc[mi][n][0], acc[mi][n][1]);
            *(__nv_bfloat162*)&hp[(size_t)(gr + 8) * C + gc] =
                __floats2bfloat162_rn(acc[mi][n][2], acc[mi][n][3]);
        }
    }
}

// ---------------------------------------------------------------------------
__global__ __launch_bounds__(256, 2)
void proj_mma(const float* __restrict__ x, const float* __restrict__ bproj,
              float* __restrict__ out) {
    __shared__ __align__(16) __nv_bfloat16 As[2][BM * BKP];
    __shared__ __align__(16) __nv_bfloat16 Bs[2][BN * BKP];
    const int b = blockIdx.z, m0 = blockIdx.y * BM, n0 = blockIdx.x * BN;
    const int tid = threadIdx.x, lane = tid & 31, wid = tid >> 5;
    const int wm = wid >> 1, wn = wid & 1;
    const __nv_bfloat16* hp = g_h + (size_t)b * HW * C;

    float acc[2][8][4];
#pragma unroll
    for (int i = 0; i < 2; i++)
#pragma unroll
        for (int j = 0; j < 8; j++)
#pragma unroll
            for (int q = 0; q < 4; q++) acc[i][j][q] = 0.f;

    const unsigned aBase = su32(As), bBase = su32(Bs);
    const int ar = tid >> 2, aq = tid & 3;

    auto issue = [&](int k0, int st) {
        unsigned off = (unsigned)(ar * BKP + aq * 8) * 2;
        unsigned ad = aBase + (unsigned)(st * BM * BKP) * 2 + off;
        unsigned bd = bBase + (unsigned)(st * BN * BKP) * 2 + off;
        const __nv_bfloat16* as = &g_wproj[(size_t)(m0 + ar) * C + k0 + aq * 8];
        const __nv_bfloat16* bs = &hp[(size_t)(n0 + ar) * C + k0 + aq * 8];
        cp16(ad, as);                                cp16(bd, bs);
        cp16(ad + 64 * BKP * 2, as + (size_t)64 * C);
        cp16(bd + 64 * BKP * 2, bs + (size_t)64 * C);
        CP_COMMIT();
    };

    issue(0, 0);
    const int S = C / BK;
    for (int s = 0; s < S; s++) {
        CP_WAIT0();
        __syncthreads();
        if (s + 1 < S) issue((s + 1) * BK, (s + 1) & 1);
        mma_block<false, false>(aBase + (unsigned)((s & 1) * BM * BKP) * 2,
                                bBase + (unsigned)((s & 1) * BN * BKP) * 2,
                                acc, lane, wm, wn);
    }

    const float* xb = x + (size_t)b * C * HW;
    float* ob = out + (size_t)b * C * HW;
    const int rr = lane >> 2, cc = (lane & 3) * 2;
#pragma unroll
    for (int mi = 0; mi < 2; mi++) {
        int gr = m0 + wm * 32 + mi * 16 + rr;
        float b0v = bproj[gr], b1v = bproj[gr + 8];
#pragma unroll
        for (int n = 0; n < 8; n++) {
            int gc = n0 + wn * 64 + n * 8 + cc;
            float2 x0 = *(const float2*)&xb[(size_t)gr * HW + gc];
            float2 x1 = *(const float2*)&xb[(size_t)(gr + 8) * HW + gc];
            *(float2*)&ob[(size_t)gr * HW + gc] =
                make_float2(x0.x + b0v + acc[mi][n][0], x0.y + b0v + acc[mi][n][1]);
            *(float2*)&ob[(size_t)(gr + 8) * HW + gc] =
                make_float2(x1.x + b1v + acc[mi][n][2], x1.y + b1v + acc[mi][n][3]);
        }
    }
}

// ---------------------------------------------------------------------------
extern "C" void kernel_launch(void* const* d_in, const int* in_sizes, int n_in,
                              void* d_out, int out_size) {
    const float* x      = (const float*)d_in[0];
    const float* w_qkv  = (const float*)d_in[1];
    const float* b_qkv  = (const float*)d_in[2];
    const float* w_proj = (const float*)d_in[3];
    const float* b_proj = (const float*)d_in[4];
    float* out = (float*)d_out;

    cudaFuncSetAttribute(conv_mma2, cudaFuncAttributeMaxDynamicSharedMemorySize,
                         SMEM_CONV);

    pack_w_kernel<<<(C3 * KTOT + 255) / 256, 256>>>(w_qkv);
    pack_wproj_kernel<<<(C * C + 255) / 256, 256>>>(w_proj);
    xt_kernel<<<dim3(HW / 64, C / 64, Bsz), 256>>>(x);
    conv_mma2<<<dim3(HW / CBN, C3 / BM, Bsz), 512, SMEM_CONV>>>(b_qkv);
    scores_mma<<<dim3(HW / BN, HW / BM, Bsz), 256>>>();
    softmax_kernel<<<Bsz * HW, 256>>>();
    av_mma<<<dim3(C / BN, HW / BM, Bsz), 256>>>();
    proj_mma<<<dim3(HW / BN, C / BM, Bsz), 256>>>(x, b_proj, out);
}